// round 12
// baseline (speedup 1.0000x reference)
#include <cuda_runtime.h>
#include <cuda_bf16.h>
#include <cstdint>

#define NUM_TOKENS 131072
#define NUM_EXPERTS 256
#define TOPK 8
#define LOG2E 1.4426950408889634f

__device__ __forceinline__ float ex2(float x) {
    float y; asm("ex2.approx.ftz.f32 %0, %1;" : "=f"(y) : "f"(x)); return y;
}

__global__ void __launch_bounds__(256, 5)
moe_topk_softmax_kernel(const float* __restrict__ gating,
                        float* __restrict__ out) {
    // One buffer per token; 16 tokens per 256-thread block (2 per warp).
    __shared__ __align__(16) float sv[16][72];   // survivor values + pad (288B rows, 16B aligned)
    __shared__ int   si[16][64];                 // survivor expert indices
    const unsigned FULL = 0xffffffffu;
    const int warp = threadIdx.x >> 5;
    const int lane = threadIdx.x & 31;
    const int half = lane >> 4;          // 0: token A, 1: token B
    const int hl   = lane & 15;          // lane within half
    const int tl   = warp * 2 + half;    // token-local id 0..15
    const int token = blockIdx.x * 16 + tl;
    const float NEG_INF = __int_as_float(0xff800000);

    // Coalesced load: each half-warp reads one 1KB row; 4 float4 per lane.
    const float4* row = reinterpret_cast<const float4*>(gating) + (size_t)token * 64;
    float4 P0 = __ldg(&row[hl]);
    float4 P1 = __ldg(&row[hl + 16]);
    float4 P2 = __ldg(&row[hl + 32]);
    float4 P3 = __ldg(&row[hl + 48]);
    float v[16] = {P0.x,P0.y,P0.z,P0.w, P1.x,P1.y,P1.z,P1.w,
                   P2.x,P2.y,P2.z,P2.w, P3.x,P3.y,P3.z,P3.w};
    // Element v[4a+b] has global expert index 64a + 4*hl + b.

    // Two 8-element group maxima (also feed the rare fallback) + lane max
    float g0 = v[0], g1 = v[8];
#pragma unroll
    for (int j = 1; j < 8; j++) { g0 = fmaxf(g0, v[j]); g1 = fmaxf(g1, v[8 + j]); }
    float lm = fmaxf(g0, g1);

    // thr = min of the 8 lane-pair maxima (8 disjoint 32-elem groups => thr <= t8).
    // rmax = row max. All xor offsets < 16 stay within the half-warp.
    float qm = fmaxf(lm, __shfl_xor_sync(FULL, lm, 1));
    float thr = qm, rmax = qm;
#pragma unroll
    for (int o = 2; o < 16; o <<= 1) {
        thr  = fminf(thr,  __shfl_xor_sync(FULL, thr,  o));
        rmax = fmaxf(rmax, __shfl_xor_sync(FULL, rmax, o));
    }

    // ---- Softmax denominator early (frees v's tail role; overlaps MUFU) ----
    const float rm2 = rmax * LOG2E;
    float sm = 0.f;
#pragma unroll
    for (int j = 0; j < 16; j++) sm += ex2(fmaf(v[j], LOG2E, -rm2));
#pragma unroll
    for (int o = 1; o < 16; o <<= 1) sm += __shfl_xor_sync(FULL, sm, o);
    const float inv = __fdividef(1.0f, sm);

    // ---- Flags + half-warp exclusive prefix scan ----
    unsigned bm; int c, off, S;
#define SCAN_FLAGS(T)                                                      \
    {                                                                      \
        bm = 0u;                                                           \
        _Pragma("unroll")                                                  \
        for (int j = 0; j < 16; j++) bm |= (v[j] >= (T)) ? (1u << j) : 0u; \
        c = __popc(bm);                                                    \
        off = c;                                                           \
        _Pragma("unroll")                                                  \
        for (int d = 1; d < 16; d <<= 1) {                                 \
            int t_ = __shfl_up_sync(FULL, off, d);                         \
            if (hl >= d) off += t_;                                        \
        }                                                                  \
        S = __shfl_sync(FULL, off, lane | 15);                             \
        off -= c;                                                          \
    }
    SCAN_FLAGS(thr);

    int Smax = max(S, __shfl_xor_sync(FULL, S, 16));  // warp-uniform
    if (Smax > 64) {
        // Rare fallback: m8 = 8th-largest of this token's 32 eight-elem group maxima.
        // m8 <= t8 (top-8 group maxima are 8 distinct elements); survivors <= 8*8 = 64.
        // Redistribute each token's 32 group maxima across the full warp, bitonic sort.
        float s1v = __shfl_sync(FULL, g1, hl);        // lanes>=16 fetch g1 of lane-16
        float x0  = half ? s1v : g0;                  // token A's 32 group maxima
        float s0v = __shfl_sync(FULL, g0, lane | 16); // lanes<16 fetch g0 of lane+16
        float x1  = half ? g1 : s0v;                  // token B's 32 group maxima
#define BITONIC32(s)                                                        \
        _Pragma("unroll")                                                   \
        for (int k = 2; k <= 32; k <<= 1) {                                 \
            _Pragma("unroll")                                               \
            for (int j = k >> 1; j > 0; j >>= 1) {                          \
                float o_ = __shfl_xor_sync(FULL, (s), j);                   \
                bool up    = ((lane & k) == 0);                             \
                bool lower = ((lane & j) == 0);                             \
                (s) = (lower == up) ? fminf((s), o_) : fmaxf((s), o_);      \
            }                                                               \
        }
        BITONIC32(x0);
        BITONIC32(x1);
#undef BITONIC32
        float m8a = __shfl_sync(FULL, x0, 24);  // ascending: 8th largest at lane 24
        float m8b = __shfl_sync(FULL, x1, 24);
        float T2 = half ? m8b : m8a;
        SCAN_FLAGS(T2);
        Smax = max(S, __shfl_xor_sync(FULL, S, 16));
    }
#undef SCAN_FLAGS
    const int Sc = (S < 64) ? S : 64;   // safety clamp (fallback guarantees <=64)

    // ---- Compact survivors into this token's buffer ----
    float* WV = sv[tl];
    int*   WI = si[tl];
    const int h4 = hl * 4;
#pragma unroll
    for (int j = 0; j < 16; j++) {
        if (bm & (1u << j)) {
            int g = ((j >> 2) << 6) + h4 + (j & 3);
            if (off < 64) { WV[off] = v[j]; WI[off] = g; }
            off++;
        }
    }
    if (hl < 4) WV[Sc + hl] = NEG_INF;   // pad for float4 loop (Sc+3 <= 67 < 72)
    __syncwarp();

    // ---- Rank candidates by counting strictly-greater survivors (LDS.128 stream) ----
    const float4* WV4 = reinterpret_cast<const float4*>(WV);
    float c1v = NEG_INF, c2v = NEG_INF, c3v = NEG_INF, c4v = NEG_INF;
    int   c1g = 0, c2g = 0, c3g = 0, c4g = 0;
    int   r1 = 99, r2 = 99, r3 = 99, r4 = 99;
    if (hl < Sc) { c1v = WV[hl]; c1g = WI[hl]; }
    const int nIter = (Sc + 3) >> 2;
    if (Smax <= 16) {
        int ra = 0;
        for (int i = 0; i < nIter; i++) {
            float4 e = WV4[i];
            ra += (e.x > c1v) + (e.y > c1v) + (e.z > c1v) + (e.w > c1v);
        }
        if (hl < Sc) r1 = ra;
    } else if (Smax <= 32) {
        if (hl + 16 < Sc) { c2v = WV[hl + 16]; c2g = WI[hl + 16]; }
        int ra = 0, rb = 0;
        for (int i = 0; i < nIter; i++) {
            float4 e = WV4[i];
            ra += (e.x > c1v) + (e.y > c1v) + (e.z > c1v) + (e.w > c1v);
            rb += (e.x > c2v) + (e.y > c2v) + (e.z > c2v) + (e.w > c2v);
        }
        if (hl < Sc)      r1 = ra;
        if (hl + 16 < Sc) r2 = rb;
    } else {
        if (hl + 16 < Sc) { c2v = WV[hl + 16]; c2g = WI[hl + 16]; }
        if (hl + 32 < Sc) { c3v = WV[hl + 32]; c3g = WI[hl + 32]; }
        if (hl + 48 < Sc) { c4v = WV[hl + 48]; c4g = WI[hl + 48]; }
        int ra = 0, rb = 0, rc = 0, rd = 0;
        for (int i = 0; i < nIter; i++) {
            float4 e = WV4[i];
            ra += (e.x > c1v) + (e.y > c1v) + (e.z > c1v) + (e.w > c1v);
            rb += (e.x > c2v) + (e.y > c2v) + (e.z > c2v) + (e.w > c2v);
            rc += (e.x > c3v) + (e.y > c3v) + (e.z > c3v) + (e.w > c3v);
            rd += (e.x > c4v) + (e.y > c4v) + (e.z > c4v) + (e.w > c4v);
        }
        if (hl < Sc)      r1 = ra;
        if (hl + 16 < Sc) r2 = rb;
        if (hl + 32 < Sc) r3 = rc;
        if (hl + 48 < Sc) r4 = rd;
    }

    // ---- Exactness check per half: ranks 0..7 covered exactly once ----
    unsigned wbit = ((r1 < 8) ? (1u << r1) : 0u) | ((r2 < 8) ? (1u << r2) : 0u)
                  | ((r3 < 8) ? (1u << r3) : 0u) | ((r4 < 8) ? (1u << r4) : 0u);
    unsigned cnt  = (unsigned)(r1 < 8) + (unsigned)(r2 < 8)
                  + (unsigned)(r3 < 8) + (unsigned)(r4 < 8);
#pragma unroll
    for (int o = 1; o < 16; o <<= 1) {
        wbit |= __shfl_xor_sync(FULL, wbit, o);
        cnt  += __shfl_xor_sync(FULL, cnt,  o);
    }
    if (!(wbit == 0xFFu && cnt == 8u)) {
        // Tie-aware exact ranking (value desc, index asc) — matches jax.lax.top_k.
        int ra = 0, rb = 0, rc = 0, rd = 0;
        for (int i = 0; i < Sc; i++) {
            float ev = WV[i]; int eg = WI[i];
            ra += (ev > c1v) || (ev == c1v && eg < c1g);
            rb += (ev > c2v) || (ev == c2v && eg < c2g);
            rc += (ev > c3v) || (ev == c3v && eg < c3g);
            rd += (ev > c4v) || (ev == c4v && eg < c4g);
        }
        r1 = (hl < Sc)      ? ra : 99;
        r2 = (hl + 16 < Sc) ? rb : 99;
        r3 = (hl + 32 < Sc) ? rc : 99;
        r4 = (hl + 48 < Sc) ? rd : 99;
    }

    // ---- Winners write their slot directly ----
    // Layout: [weights (TOKENS*8) | indices-as-float (TOKENS*8)]
    float* wbase = out + (size_t)token * TOPK;
    float* ibase = out + (size_t)NUM_TOKENS * TOPK + (size_t)token * TOPK;
    if (r1 < 8) {
        wbase[r1] = ex2(fmaf(c1v, LOG2E, -rm2)) * inv;
        ibase[r1] = (float)c1g;
    }
    if (r2 < 8) {
        wbase[r2] = ex2(fmaf(c2v, LOG2E, -rm2)) * inv;
        ibase[r2] = (float)c2g;
    }
    if (Smax > 32) {
        if (r3 < 8) {
            wbase[r3] = ex2(fmaf(c3v, LOG2E, -rm2)) * inv;
            ibase[r3] = (float)c3g;
        }
        if (r4 < 8) {
            wbase[r4] = ex2(fmaf(c4v, LOG2E, -rm2)) * inv;
            ibase[r4] = (float)c4g;
        }
    }
}

extern "C" void kernel_launch(void* const* d_in, const int* in_sizes, int n_in,
                              void* d_out, int out_size) {
    const float* gating = (const float*)d_in[0];
    float* out = (float*)d_out;
    const int blocks = NUM_TOKENS / 16;   // 16 tokens per 256-thread block (2 per warp)
    moe_topk_softmax_kernel<<<blocks, 256>>>(gating, out);
}

// round 13
// speedup vs baseline: 1.0023x; 1.0023x over previous
#include <cuda_runtime.h>
#include <cuda_bf16.h>
#include <cstdint>

#define NUM_TOKENS 131072
#define NUM_EXPERTS 256
#define TOPK 8
#define LOG2E 1.4426950408889634f

__device__ __forceinline__ float ex2(float x) {
    float y; asm("ex2.approx.ftz.f32 %0, %1;" : "=f"(y) : "f"(x)); return y;
}
__device__ __forceinline__ float lg2(float x) {
    float y; asm("lg2.approx.ftz.f32 %0, %1;" : "=f"(y) : "f"(x)); return y;
}

__global__ void __launch_bounds__(256, 6)
moe_topk_softmax_kernel(const float* __restrict__ gating,
                        float* __restrict__ out) {
    __shared__ __align__(16) float sv[8][72];   // survivor values (+pad); 288B rows, 16B aligned
    __shared__ int   si[8][64];                 // survivor expert indices
    const unsigned FULL = 0xffffffffu;
    const int wib  = threadIdx.x >> 5;
    const int lane = threadIdx.x & 31;
    const int warp = blockIdx.x * 8 + wib;
    const float NEG_INF = __int_as_float(0xff800000);

    // Coalesced row load: 64 float4 per row
    const float4* row = reinterpret_cast<const float4*>(gating + (size_t)warp * NUM_EXPERTS);
    float4 A = __ldg(&row[lane]);
    float4 B = __ldg(&row[lane + 32]);
    float v[8] = {A.x, A.y, A.z, A.w, B.x, B.y, B.z, B.w};

    // Per-lane max
    float lm = v[0];
#pragma unroll
    for (int j = 1; j < 8; j++) lm = fmaxf(lm, v[j]);

    // thr = min of the 8 quad maxima (8 disjoint 32-elem groups => thr <= t8; also
    // every quad max >= thr => S >= 8). rmax = row max.
    float qm = fmaxf(lm, __shfl_xor_sync(FULL, lm, 1));
    qm = fmaxf(qm, __shfl_xor_sync(FULL, qm, 2));
    float thr = qm, rmax = qm;
#pragma unroll
    for (int o = 4; o < 32; o <<= 1) {
        thr  = fminf(thr,  __shfl_xor_sync(FULL, thr,  o));
        rmax = fmaxf(rmax, __shfl_xor_sync(FULL, rmax, o));
    }

    // ---- Softmax denominator early; fold into exponent offset ----
    const float rm2 = rmax * LOG2E;
    float sm = 0.f;
#pragma unroll
    for (int j = 0; j < 8; j++) sm += ex2(fmaf(v[j], LOG2E, -rm2));
#pragma unroll
    for (int o = 1; o < 32; o <<= 1) sm += __shfl_xor_sync(FULL, sm, o);
    const float woff = -rm2 - lg2(sm);   // w = ex2(fma(v, LOG2E, woff))

    // ---- Flag mask + exclusive prefix scan of survivor counts ----
    unsigned bm; int c, off, S;
#define SCAN_FLAGS(T)                                                      \
    {                                                                      \
        bm = 0u;                                                           \
        _Pragma("unroll")                                                  \
        for (int j = 0; j < 8; j++) bm |= (v[j] >= (T)) ? (1u << j) : 0u;  \
        c = __popc(bm);                                                    \
        off = c;                                                           \
        _Pragma("unroll")                                                  \
        for (int d = 1; d < 32; d <<= 1) {                                 \
            int t_ = __shfl_up_sync(FULL, off, d);                         \
            if (lane >= d) off += t_;                                      \
        }                                                                  \
        S = __shfl_sync(FULL, off, 31);                                    \
        off -= c;                                                          \
    }
    SCAN_FLAGS(thr);

    // Rare (~0.3%) fallback: exact 8th-largest of the 32 lane maxima (bounds S <= ~57)
    if (S > 64) {
        float s = lm;
#pragma unroll
        for (int k = 2; k <= 32; k <<= 1) {
#pragma unroll
            for (int j = k >> 1; j > 0; j >>= 1) {
                float o_ = __shfl_xor_sync(FULL, s, j);
                bool up    = ((lane & k) == 0);
                bool lower = ((lane & j) == 0);
                s = (lower == up) ? fminf(s, o_) : fmaxf(s, o_);
            }
        }
        float m8f = __shfl_sync(FULL, s, 24);   // ascending sort: 8th largest at lane 24
        SCAN_FLAGS(m8f);
    }
#undef SCAN_FLAGS
    const int Sc = (S < 64) ? S : 64;   // safety clamp (fallback guarantees <= ~57)

    // ---- Pre-pad the whole row with -inf, then compact survivors ----
    float* WV = sv[wib];
    int*   WI = si[wib];
    WV[lane] = NEG_INF;
    WV[lane + 32] = NEG_INF;
    if (lane < 8) WV[lane + 64] = NEG_INF;
    __syncwarp();

    const int base = lane * 4;
#pragma unroll
    for (int j = 0; j < 8; j++) {
        if (bm & (1u << j)) {
            int g = (j < 4) ? (base + j) : (124 + base + j);   // 128 + base + (j-4)
            if (off < 64) { WV[off] = v[j]; WI[off] = g; }
            off++;
        }
    }
    __syncwarp();

    // ---- Rank candidates by counting strictly-greater survivors ----
    const float4* WV4 = reinterpret_cast<const float4*>(WV);
    float c1v = NEG_INF, c2v = NEG_INF;
    int   c1g = 0, c2g = 0;
    int   r1 = 99, r2 = 99;
    if (lane < Sc) { c1v = WV[lane]; c1g = WI[lane]; }
    if (S <= 32) {
        // Common path (~97%): fully unrolled, 8 independent LDS.128, no loop overhead.
        float4 e0 = WV4[0], e1 = WV4[1], e2 = WV4[2], e3 = WV4[3];
        float4 e4 = WV4[4], e5 = WV4[5], e6 = WV4[6], e7 = WV4[7];
        int rk = (e0.x > c1v) + (e0.y > c1v) + (e0.z > c1v) + (e0.w > c1v)
               + (e1.x > c1v) + (e1.y > c1v) + (e1.z > c1v) + (e1.w > c1v)
               + (e2.x > c1v) + (e2.y > c1v) + (e2.z > c1v) + (e2.w > c1v)
               + (e3.x > c1v) + (e3.y > c1v) + (e3.z > c1v) + (e3.w > c1v)
               + (e4.x > c1v) + (e4.y > c1v) + (e4.z > c1v) + (e4.w > c1v)
               + (e5.x > c1v) + (e5.y > c1v) + (e5.z > c1v) + (e5.w > c1v)
               + (e6.x > c1v) + (e6.y > c1v) + (e6.z > c1v) + (e6.w > c1v)
               + (e7.x > c1v) + (e7.y > c1v) + (e7.z > c1v) + (e7.w > c1v);
        if (lane < Sc) r1 = rk;
    } else {
        // Rare: up to 64 survivors, two candidates per lane.
        if (lane + 32 < Sc) { c2v = WV[lane + 32]; c2g = WI[lane + 32]; }
        int ra = 0, rb = 0;
        const int nIter = (Sc + 3) >> 2;
        for (int i = 0; i < nIter; i++) {
            float4 e = WV4[i];
            ra += (e.x > c1v) + (e.y > c1v) + (e.z > c1v) + (e.w > c1v);
            rb += (e.x > c2v) + (e.y > c2v) + (e.z > c2v) + (e.w > c2v);
        }
        if (lane < Sc)      r1 = ra;
        if (lane + 32 < Sc) r2 = rb;
    }

    // ---- Exactness check: winners must cover ranks 0..7 exactly once ----
    unsigned wbit = ((r1 < 8) ? (1u << r1) : 0u) | ((r2 < 8) ? (1u << r2) : 0u);
    unsigned cnt  = (unsigned)(r1 < 8) + (unsigned)(r2 < 8);
    unsigned mask = __reduce_or_sync(FULL, wbit);
    unsigned tot  = __reduce_add_sync(FULL, cnt);
    if (!(mask == 0xFFu && tot == 8u)) {
        // Tie-aware exact ranking (value desc, index asc) — matches jax.lax.top_k.
        int ra = 0, rb = 0;
        for (int i = 0; i < Sc; i++) {
            float ev = WV[i]; int eg = WI[i];
            ra += (ev > c1v) || (ev == c1v && eg < c1g);
            rb += (ev > c2v) || (ev == c2v && eg < c2g);
        }
        r1 = (lane < Sc)      ? ra : 99;
        r2 = (lane + 32 < Sc) ? rb : 99;
    }

    // ---- Winners write their slot directly ----
    // Layout: [weights (TOKENS*8) | indices-as-float (TOKENS*8)]
    float* wbase = out + (size_t)warp * TOPK;
    float* ibase = out + (size_t)NUM_TOKENS * TOPK + (size_t)warp * TOPK;
    if (r1 < 8) {
        wbase[r1] = ex2(fmaf(c1v, LOG2E, woff));
        ibase[r1] = (float)c1g;
    }
    if (r2 < 8) {
        wbase[r2] = ex2(fmaf(c2v, LOG2E, woff));
        ibase[r2] = (float)c2g;
    }
}

extern "C" void kernel_launch(void* const* d_in, const int* in_sizes, int n_in,
                              void* d_out, int out_size) {
    const float* gating = (const float*)d_in[0];
    float* out = (float*)d_out;
    const int blocks = NUM_TOKENS / 8;   // 8 warps (tokens) per 256-thread block
    moe_topk_softmax_kernel<<<blocks, 256>>>(gating, out);
}

// round 14
// speedup vs baseline: 1.1738x; 1.1711x over previous
#include <cuda_runtime.h>
#include <cuda_fp16.h>
#include <cstdint>

#define NUM_TOKENS 131072
#define NUM_EXPERTS 256
#define TOPK 8
#define LOG2E 1.4426950408889634f

__device__ __forceinline__ float ex2(float x) {
    float y; asm("ex2.approx.ftz.f32 %0, %1;" : "=f"(y) : "f"(x)); return y;
}
__device__ __forceinline__ float lg2(float x) {
    float y; asm("lg2.approx.ftz.f32 %0, %1;" : "=f"(y) : "f"(x)); return y;
}

__global__ void __launch_bounds__(256, 6)
moe_topk_softmax_kernel(const float* __restrict__ gating,
                        float* __restrict__ out) {
    __shared__ __align__(16) float   sv[8][72];  // f32 survivor values (+pad region)
    __shared__ __align__(16) int     si[8][64];  // survivor expert indices
    __shared__ __align__(16) __half2 sh[8][16];  // fp16-packed survivors, slots 0..31
    const unsigned FULL = 0xffffffffu;
    const int wib  = threadIdx.x >> 5;
    const int lane = threadIdx.x & 31;
    const int warp = blockIdx.x * 8 + wib;
    const float NEG_INF = __int_as_float(0xff800000);

    // Coalesced row load: 64 float4 per row
    const float4* row = reinterpret_cast<const float4*>(gating + (size_t)warp * NUM_EXPERTS);
    float4 A = __ldg(&row[lane]);
    float4 B = __ldg(&row[lane + 32]);
    float v[8] = {A.x, A.y, A.z, A.w, B.x, B.y, B.z, B.w};

    // Per-lane max
    float lm = v[0];
#pragma unroll
    for (int j = 1; j < 8; j++) lm = fmaxf(lm, v[j]);

    // thr = min of the 8 quad maxima (8 disjoint 32-elem groups => thr <= t8, and
    // all 8 quad maxima >= thr => S >= 8). rmax = row max.
    float qm = fmaxf(lm, __shfl_xor_sync(FULL, lm, 1));
    qm = fmaxf(qm, __shfl_xor_sync(FULL, qm, 2));
    float thr = qm, rmax = qm;
#pragma unroll
    for (int o = 4; o < 32; o <<= 1) {
        thr  = fminf(thr,  __shfl_xor_sync(FULL, thr,  o));
        rmax = fmaxf(rmax, __shfl_xor_sync(FULL, rmax, o));
    }

    // ---- Softmax denominator early; fold into exponent offset ----
    const float rm2 = rmax * LOG2E;
    float sm = 0.f;
#pragma unroll
    for (int j = 0; j < 8; j++) sm += ex2(fmaf(v[j], LOG2E, -rm2));
#pragma unroll
    for (int o = 1; o < 32; o <<= 1) sm += __shfl_xor_sync(FULL, sm, o);
    const float woff = -rm2 - lg2(sm);   // weight = ex2(fma(v, LOG2E, woff))

    // ---- Flag mask + exclusive prefix scan of survivor counts ----
    unsigned bm; int c, off, S;
#define SCAN_FLAGS(T)                                                      \
    {                                                                      \
        bm = 0u;                                                           \
        _Pragma("unroll")                                                  \
        for (int j = 0; j < 8; j++) bm |= (v[j] >= (T)) ? (1u << j) : 0u;  \
        c = __popc(bm);                                                    \
        off = c;                                                           \
        _Pragma("unroll")                                                  \
        for (int d = 1; d < 32; d <<= 1) {                                 \
            int t_ = __shfl_up_sync(FULL, off, d);                         \
            if (lane >= d) off += t_;                                      \
        }                                                                  \
        S = __shfl_sync(FULL, off, 31);                                    \
        off -= c;                                                          \
    }
    SCAN_FLAGS(thr);

    // Rare fallback: m8 = exact 8th-largest of the 32 lane maxima. Only the 8
    // lanes whose max >= m8 can contribute, each <= 8 elements => S <= 64 PROVEN.
    if (S > 64) {
        float s = lm;
#pragma unroll
        for (int k = 2; k <= 32; k <<= 1) {
#pragma unroll
            for (int j = k >> 1; j > 0; j >>= 1) {
                float o_ = __shfl_xor_sync(FULL, s, j);
                bool up    = ((lane & k) == 0);
                bool lower = ((lane & j) == 0);
                s = (lower == up) ? fminf(s, o_) : fmaxf(s, o_);
            }
        }
        float m8f = __shfl_sync(FULL, s, 24);   // ascending: 8th largest at lane 24
        SCAN_FLAGS(m8f);
    }
#undef SCAN_FLAGS
    // Invariants: 8 <= S <= 64 (no clamp, no per-store guard needed).

    float* WV = sv[wib];
    int*   WI = si[wib];
    WV[lane] = NEG_INF;                       // pad slots 0..31
    if (S > 32) WV[lane + 32] = NEG_INF;      // pad slots 32..63 (rare, warp-uniform)
    __syncwarp();

    // ---- Compact survivors (value + index); off < S <= 64 always in-bounds ----
    const int base = lane * 4;
#pragma unroll
    for (int j = 0; j < 8; j++) {
        if (bm & (1u << j)) {
            int g = (j < 4) ? (base + j) : (124 + base + j);   // 128 + base + (j-4)
            WV[off] = v[j]; WI[off] = g;
            off++;
        }
    }
    __syncwarp();

    int r1 = 99, r2 = 99;
    if (S <= 32) {
        // ---- fp16x2 SIMD ranking (common ~97%) ----
        // Convert slots 0..31 (real + -inf pad) to packed half2.
        __half2* SH = sh[wib];
        if (lane < 16) {
            float2 fp = reinterpret_cast<const float2*>(WV)[lane];
            SH[lane] = __floats2half2_rn(fp.x, fp.y);   // .x -> low = slot 2*lane
        }
        __syncwarp();
        // Candidate = slot `lane` (fp16). Pad candidates (-inf) self-rank >= S >= 8.
        __half  ch = reinterpret_cast<const __half*>(SH)[lane];
        __half2 c2 = __half2half2(ch);
        const uint4* q = reinterpret_cast<const uint4*>(SH);
        uint4 q0 = q[0], q1 = q[1], q2 = q[2], q3 = q[3];
        unsigned u[16] = {q0.x,q0.y,q0.z,q0.w, q1.x,q1.y,q1.z,q1.w,
                          q2.x,q2.y,q2.z,q2.w, q3.x,q3.y,q3.z,q3.w};
        __half2 acc0 = __float2half2_rn(0.f), acc1 = __float2half2_rn(0.f);
#pragma unroll
        for (int i = 0; i < 16; i += 2) {
            __half2 e0 = *reinterpret_cast<const __half2*>(&u[i]);
            __half2 e1 = *reinterpret_cast<const __half2*>(&u[i + 1]);
            acc0 = __hadd2(acc0, __hgt2(e0, c2));
            acc1 = __hadd2(acc1, __hgt2(e1, c2));
        }
        __half2 acc = __hadd2(acc0, acc1);
        r1 = (int)(__low2float(acc) + __high2float(acc));
    } else {
        // ---- Rare: up to 64 survivors, exact f32 ranking, 2 candidates/lane ----
        float c1v = WV[lane], c2v = WV[lane + 32];
        int ra = 0, rb = 0;
        const float4* WV4 = reinterpret_cast<const float4*>(WV);
        const int nIter = (S + 3) >> 2;
        for (int i = 0; i < nIter; i++) {
            float4 e = WV4[i];
            ra += (e.x > c1v) + (e.y > c1v) + (e.z > c1v) + (e.w > c1v);
            rb += (e.x > c2v) + (e.y > c2v) + (e.z > c2v) + (e.w > c2v);
        }
        r1 = ra;
        r2 = rb;
    }

    // ---- Exactness check: winners must cover ranks 0..7 exactly once.
    // Any fp16 collision or f32 tie that could corrupt the top-8 breaks this.
    unsigned wbit = ((r1 < 8) ? (1u << r1) : 0u) | ((r2 < 8) ? (1u << r2) : 0u);
    unsigned cnt  = (unsigned)(r1 < 8) + (unsigned)(r2 < 8);
    unsigned mask = __reduce_or_sync(FULL, wbit);
    unsigned tot  = __reduce_add_sync(FULL, cnt);
    if (!(mask == 0xFFu && tot == 8u)) {
        // Exact tie-aware ranking (value desc, index asc) — matches jax.lax.top_k.
        float c1v = WV[lane];
        int   c1g = WI[lane];
        float c2v = (S > 32) ? WV[lane + 32] : NEG_INF;
        int   c2g = (S > 32) ? WI[lane + 32] : 0;
        int ra = 0, rb = 0;
        for (int i = 0; i < S; i++) {
            float ev = WV[i]; int eg = WI[i];
            ra += (ev > c1v) || (ev == c1v && eg < c1g);
            rb += (ev > c2v) || (ev == c2v && eg < c2g);
        }
        r1 = ra;
        r2 = (S > 32) ? rb : 99;
    }

    // ---- Winners write their slot directly ----
    // Layout: [weights (TOKENS*8) | indices-as-float (TOKENS*8)]
    float* wbase = out + (size_t)warp * TOPK;
    float* ibase = out + (size_t)NUM_TOKENS * TOPK + (size_t)warp * TOPK;
    if (r1 < 8) {
        wbase[r1] = ex2(fmaf(WV[lane], LOG2E, woff));
        ibase[r1] = (float)WI[lane];
    }
    if (r2 < 8) {
        wbase[r2] = ex2(fmaf(WV[lane + 32], LOG2E, woff));
        ibase[r2] = (float)WI[lane + 32];
    }
}

extern "C" void kernel_launch(void* const* d_in, const int* in_sizes, int n_in,
                              void* d_out, int out_size) {
    const float* gating = (const float*)d_in[0];
    float* out = (float*)d_out;
    const int blocks = NUM_TOKENS / 8;   // 8 warps (tokens) per 256-thread block
    moe_topk_softmax_kernel<<<blocks, 256>>>(gating, out);
}